// round 4
// baseline (speedup 1.0000x reference)
#include <cuda_runtime.h>
#include <cuda_bf16.h>
#include <math.h>
#include <stdint.h>

#define NB   512
#define NT   60
#define NE   300
#define NH   512
#define NM   256
#define NB2  1024
#define NG   2048
#define NHC  2053

#define KPH  512
#define KCH  1536
#define NCH  24
#define KPX  320
#define KCX  960
#define NCX  15

#define STAGES 3
#define STAGE_BYTES 32768
#define GEMM_SMEM (STAGES*STAGE_BYTES)
#define ZS 136                       // z-tile smem row stride (floats), 16B-aligned rows
#define PERSIST_SMEM (GEMM_SMEM + 128*ZS*4)
#define RCTAS 128

__device__ float g_xW[(size_t)NT * NB2 * NG];      // permuted gate-interleaved cols
__device__ float g_h [NB2 * NH];
__device__ float g_c [NB2 * NH];
__device__ float g_hc[NB * NHC];
__device__ float g_e1[NB * NM];
__device__ __nv_bfloat16 g_Abuf[2][(size_t)NB2 * KCH];   // ping-pong A' [hi|hi|lo]
__device__ __nv_bfloat16 g_Bh[(size_t)NG * KCH];         // Wh' [hi|lo|hi], permuted N
__device__ __nv_bfloat16 g_Ax[(size_t)NT * NB2 * KCX];
__device__ __nv_bfloat16 g_Bx[(size_t)NG * KCX];         // Wx' permuted N
__device__ unsigned g_bar_arrive = 0;
__device__ unsigned g_bar_gen = 0;

__device__ __forceinline__ float sigmf(float x) { return 1.0f / (1.0f + expf(-x)); }

#define SWZ(b) ((b) ^ (((b) >> 3) & 0x70))

__device__ __forceinline__ uint32_t smem_u32(const void* p) {
    uint32_t a;
    asm("{ .reg .u64 t; cvta.to.shared.u64 t, %1; cvt.u32.u64 %0, t; }" : "=r"(a) : "l"(p));
    return a;
}
__device__ __forceinline__ void cpasync16(uint32_t dst, const void* src) {
    asm volatile("cp.async.cg.shared.global [%0], [%1], 16;"
                 :: "r"(dst), "l"(__cvta_generic_to_global(src)));
}
#define CP_COMMIT() asm volatile("cp.async.commit_group;" ::: "memory")

__device__ __forceinline__ void ldsm_x4(uint32_t& r0, uint32_t& r1, uint32_t& r2, uint32_t& r3,
                                        uint32_t addr) {
    asm volatile("ldmatrix.sync.aligned.m8n8.x4.shared.b16 {%0,%1,%2,%3}, [%4];"
                 : "=r"(r0), "=r"(r1), "=r"(r2), "=r"(r3) : "r"(addr));
}
__device__ __forceinline__ void mma_bf16(float* c, const uint32_t* a, uint32_t b0, uint32_t b1) {
    asm volatile("mma.sync.aligned.m16n8k16.row.col.f32.bf16.bf16.f32 "
                 "{%0,%1,%2,%3}, {%4,%5,%6,%7}, {%8,%9}, {%0,%1,%2,%3};"
                 : "+f"(c[0]), "+f"(c[1]), "+f"(c[2]), "+f"(c[3])
                 : "r"(a[0]), "r"(a[1]), "r"(a[2]), "r"(a[3]), "r"(b0), "r"(b1));
}

__device__ __forceinline__ void grid_barrier() {
    __syncthreads();
    if (threadIdx.x == 0) {
        __threadfence();
        unsigned gen = *((volatile unsigned*)&g_bar_gen);
        if (atomicAdd(&g_bar_arrive, 1) == RCTAS - 1) {
            g_bar_arrive = 0;
            __threadfence();
            *((volatile unsigned*)&g_bar_gen) = gen + 1;
        } else {
            while (*((volatile unsigned*)&g_bar_gen) == gen) __nanosleep(64);
        }
        __threadfence();
    }
    __syncthreads();
}

// ---------------------------------------------------------------------------
__global__ void zero_init() {
    int i = blockIdx.x * 256 + threadIdx.x;
    if (i < NB2 * NH) { g_h[i] = 0.0f; g_c[i] = 0.0f; }
}

// ---------------------------------------------------------------------------
// B' build with gate-interleaved N permutation:
// physical col n -> source col (n&3)*512 + (n>>2); k-split [hi|lo|hi]
// ---------------------------------------------------------------------------
__global__ void build_B_perm(const float* __restrict__ W, __nv_bfloat16* __restrict__ dst,
                             int Ksrc, int Kp) {
    int idx = blockIdx.x * 256 + threadIdx.x;
    if (idx >= NG * Kp) return;
    int k = idx / NG;          // n fastest for coalesced-ish source reads
    int n = idx % NG;
    int nsrc = (n & 3) * 512 + (n >> 2);
    float v = (k < Ksrc) ? W[(size_t)k * NG + nsrc] : 0.0f;
    __nv_bfloat16 hi = __float2bfloat16_rn(v);
    __nv_bfloat16 lo = __float2bfloat16_rn(v - __bfloat162float(hi));
    size_t base = (size_t)n * (3 * Kp);
    dst[base + k] = hi;
    dst[base + Kp + k] = lo;
    dst[base + 2 * Kp + k] = hi;
}

// ---------------------------------------------------------------------------
// Gathered A' for xproj, warp-per-row coalesced
// ---------------------------------------------------------------------------
__global__ void build_Ax(const int* __restrict__ in1, const int* __restrict__ in2,
                         const float* __restrict__ emb) {
    int w = blockIdx.x * 8 + (threadIdx.x >> 5);
    int lane = threadIdx.x & 31;
    if (w >= NT * NB2) return;
    int t  = w >> 10;
    int b2 = w & 1023;
    int tok = (b2 < NB) ? in1[b2 * NT + t] : in2[(b2 - NB) * NT + t];
    const float* er = emb + (size_t)tok * NE;
    size_t base = (size_t)w * KCX;
    for (int k = lane; k < KPX; k += 32) {
        float v = (k < NE) ? er[k] : 0.0f;
        __nv_bfloat16 hi = __float2bfloat16_rn(v);
        __nv_bfloat16 lo = __float2bfloat16_rn(v - __bfloat162float(hi));
        g_Ax[base + k] = hi;
        g_Ax[base + KPX + k] = hi;
        g_Ax[base + 2 * KPX + k] = lo;
    }
}

// ---------------------------------------------------------------------------
// bf16 mma.sync GEMM (xproj): C[M,2048] = A'[M,Kc] @ B'[2048,Kc]^T
// ---------------------------------------------------------------------------
__global__ void __launch_bounds__(256)
gemm_mma(const __nv_bfloat16* __restrict__ A, const __nv_bfloat16* __restrict__ B,
         float* __restrict__ C, int ldab, int NC) {
    extern __shared__ char dsm[];
    const int tid  = threadIdx.x;
    const int wid  = tid >> 5;
    const int lane = tid & 31;
    const int row0 = blockIdx.y * 128;
    const int col0 = blockIdx.x * 128;
    const int wm0  = (wid & 1) * 64;
    const int wn0  = (wid >> 1) * 32;
    const uint32_t sm = smem_u32(dsm);

    const __nv_bfloat16* aRow = A + (size_t)row0 * ldab;
    const __nv_bfloat16* bRow = B + (size_t)col0 * ldab;

    auto load_chunk = [&](int c, int st) {
        uint32_t aB = sm + st * STAGE_BYTES;
        uint32_t bB = aB + 16384;
        const __nv_bfloat16* aS = aRow + c * 64;
        const __nv_bfloat16* bS = bRow + c * 64;
        #pragma unroll
        for (int i = 0; i < 4; i++) {
            int idx = i * 256 + tid;
            int r = idx >> 3, s = idx & 7;
            cpasync16(aB + SWZ(r * 128 + s * 16), aS + (size_t)r * ldab + s * 8);
        }
        #pragma unroll
        for (int i = 0; i < 4; i++) {
            int idx = i * 256 + tid;
            int n = idx >> 3, s = idx & 7;
            cpasync16(bB + SWZ(n * 128 + s * 16), bS + (size_t)n * ldab + s * 8);
        }
    };

    float acc[4][4][4];
    #pragma unroll
    for (int i = 0; i < 4; i++)
        #pragma unroll
        for (int j = 0; j < 4; j++)
            #pragma unroll
            for (int k = 0; k < 4; k++) acc[i][j][k] = 0.0f;

    for (int s = 0; s < STAGES && s < NC; s++) { load_chunk(s, s); CP_COMMIT(); }

    const int a_row = wm0 + (lane & 15);
    const int a_colb = 16 * (lane >> 4);
    const int b_row = wn0 + lane;
    for (int c = 0; c < NC; c++) {
        int st = c % STAGES;
        int rem = NC - 1 - c;
        if (rem >= 2)      asm volatile("cp.async.wait_group 2;" ::: "memory");
        else if (rem == 1) asm volatile("cp.async.wait_group 1;" ::: "memory");
        else               asm volatile("cp.async.wait_group 0;" ::: "memory");
        __syncthreads();

        uint32_t aB = sm + st * STAGE_BYTES;
        uint32_t bB = aB + 16384;
        #pragma unroll
        for (int kk = 0; kk < 4; kk++) {
            uint32_t a[4][4];
            #pragma unroll
            for (int mf = 0; mf < 4; mf++) {
                uint32_t addr = aB + SWZ((a_row + mf * 16) * 128 + kk * 32 + a_colb);
                ldsm_x4(a[mf][0], a[mf][1], a[mf][2], a[mf][3], addr);
            }
            uint32_t blo[4], bhi[4];
            uint32_t addr0 = bB + SWZ(b_row * 128 + kk * 32);
            ldsm_x4(blo[0], blo[1], blo[2], blo[3], addr0);
            uint32_t addr1 = bB + SWZ(b_row * 128 + kk * 32 + 16);
            ldsm_x4(bhi[0], bhi[1], bhi[2], bhi[3], addr1);
            #pragma unroll
            for (int mf = 0; mf < 4; mf++)
                #pragma unroll
                for (int nf = 0; nf < 4; nf++)
                    mma_bf16(acc[mf][nf], a[mf], blo[nf], bhi[nf]);
        }
        __syncthreads();
        if (c + STAGES < NC) { load_chunk(c + STAGES, st); CP_COMMIT(); }
    }

    const int gid = lane >> 2, tig = lane & 3;
    #pragma unroll
    for (int mf = 0; mf < 4; mf++)
        #pragma unroll
        for (int nf = 0; nf < 4; nf++) {
            size_t row = (size_t)row0 + wm0 + mf * 16 + gid;
            size_t col = (size_t)col0 + wn0 + nf * 8 + tig * 2;
            *reinterpret_cast<float2*>(C + row * NG + col) =
                make_float2(acc[mf][nf][0], acc[mf][nf][1]);
            *reinterpret_cast<float2*>(C + (row + 8) * NG + col) =
                make_float2(acc[mf][nf][2], acc[mf][nf][3]);
        }
}

// ---------------------------------------------------------------------------
// Persistent recurrence: 128 CTAs = 8 row-tiles x 16 col-tiles. Each step:
// z = A'@B' (tile), fused LSTM cell on the tile's 32 units, grid barrier.
// ---------------------------------------------------------------------------
__global__ void __launch_bounds__(256, 1)
lstm_persist(const __nv_bfloat16* __restrict__ Bh, const float* __restrict__ bias,
             const int* __restrict__ sl1, const int* __restrict__ sl2) {
    extern __shared__ char dsm[];
    float* zt = (float*)(dsm + GEMM_SMEM);
    __shared__ float s_bias[128];
    __shared__ int   s_sl[128];

    const int tid  = threadIdx.x;
    const int wid  = tid >> 5;
    const int lane = tid & 31;
    const int rt = blockIdx.x >> 4, ct = blockIdx.x & 15;
    const int row0 = rt * 128, col0 = ct * 128;
    const int wm0 = (wid & 1) * 64, wn0 = (wid >> 1) * 32;
    const uint32_t sm = smem_u32(dsm);

    if (tid < 128) {
        int u = ct * 32 + (tid >> 2), g = tid & 3;
        s_bias[tid] = bias[g * 512 + u] + ((g == 2) ? 1.0f : 0.0f);  // fold forget bias
        int b = row0 + tid;
        s_sl[tid] = (b < NB) ? sl1[b] : sl2[b - NB];
    }
    __syncthreads();

    const __nv_bfloat16* bRow = Bh + (size_t)col0 * KCH;
    const int a_row = wm0 + (lane & 15);
    const int a_colb = 16 * (lane >> 4);
    const int b_row = wn0 + lane;
    const int gid = lane >> 2, tig = lane & 3;

    for (int t = 0; t < NT; t++) {
        float acc[4][4][4];
        #pragma unroll
        for (int i = 0; i < 4; i++)
            #pragma unroll
            for (int j = 0; j < 4; j++)
                #pragma unroll
                for (int k = 0; k < 4; k++) acc[i][j][k] = 0.0f;

        if (t > 0) {
            const __nv_bfloat16* aRow = g_Abuf[t & 1] + (size_t)row0 * KCH;
            auto load_chunk = [&](int c, int st) {
                uint32_t aB = sm + st * STAGE_BYTES;
                uint32_t bB = aB + 16384;
                const __nv_bfloat16* aS = aRow + c * 64;
                const __nv_bfloat16* bS = bRow + c * 64;
                #pragma unroll
                for (int i = 0; i < 4; i++) {
                    int idx = i * 256 + tid;
                    int r = idx >> 3, s = idx & 7;
                    cpasync16(aB + SWZ(r * 128 + s * 16), aS + (size_t)r * KCH + s * 8);
                }
                #pragma unroll
                for (int i = 0; i < 4; i++) {
                    int idx = i * 256 + tid;
                    int n = idx >> 3, s = idx & 7;
                    cpasync16(bB + SWZ(n * 128 + s * 16), bS + (size_t)n * KCH + s * 8);
                }
            };
            for (int s = 0; s < STAGES; s++) { load_chunk(s, s); CP_COMMIT(); }
            for (int c = 0; c < NCH; c++) {
                int st = c % STAGES;
                int rem = NCH - 1 - c;
                if (rem >= 2)      asm volatile("cp.async.wait_group 2;" ::: "memory");
                else if (rem == 1) asm volatile("cp.async.wait_group 1;" ::: "memory");
                else               asm volatile("cp.async.wait_group 0;" ::: "memory");
                __syncthreads();
                uint32_t aB = sm + st * STAGE_BYTES;
                uint32_t bB = aB + 16384;
                #pragma unroll
                for (int kk = 0; kk < 4; kk++) {
                    uint32_t a[4][4];
                    #pragma unroll
                    for (int mf = 0; mf < 4; mf++) {
                        uint32_t addr = aB + SWZ((a_row + mf * 16) * 128 + kk * 32 + a_colb);
                        ldsm_x4(a[mf][0], a[mf][1], a[mf][2], a[mf][3], addr);
                    }
                    uint32_t blo[4], bhi[4];
                    uint32_t addr0 = bB + SWZ(b_row * 128 + kk * 32);
                    ldsm_x4(blo[0], blo[1], blo[2], blo[3], addr0);
                    uint32_t addr1 = bB + SWZ(b_row * 128 + kk * 32 + 16);
                    ldsm_x4(bhi[0], bhi[1], bhi[2], bhi[3], addr1);
                    #pragma unroll
                    for (int mf = 0; mf < 4; mf++)
                        #pragma unroll
                        for (int nf = 0; nf < 4; nf++)
                            mma_bf16(acc[mf][nf], a[mf], blo[nf], bhi[nf]);
                }
                __syncthreads();
                if (c + STAGES < NCH) { load_chunk(c + STAGES, st); CP_COMMIT(); }
            }
        }

        // acc -> z smem tile
        #pragma unroll
        for (int mf = 0; mf < 4; mf++)
            #pragma unroll
            for (int nf = 0; nf < 4; nf++) {
                int r = wm0 + mf * 16 + gid;
                int cc = wn0 + nf * 8 + tig * 2;
                *reinterpret_cast<float2*>(&zt[r * ZS + cc]) =
                    make_float2(acc[mf][nf][0], acc[mf][nf][1]);
                *reinterpret_cast<float2*>(&zt[(r + 8) * ZS + cc]) =
                    make_float2(acc[mf][nf][2], acc[mf][nf][3]);
            }
        __syncthreads();

        // fused LSTM cell: 2 threads per row, 16 units each
        {
            int row = tid >> 1;
            int ul0 = (tid & 1) * 16;
            size_t b = (size_t)row0 + row;
            bool valid = t < s_sl[row];
            float hold[16], cold[16], hnew[16];
            float* hp = g_h + b * NH + ct * 32 + ul0;
            float* cp = g_c + b * NH + ct * 32 + ul0;
            #pragma unroll
            for (int q = 0; q < 4; q++) {
                *reinterpret_cast<float4*>(&hold[4 * q]) = *reinterpret_cast<const float4*>(hp + 4 * q);
                *reinterpret_cast<float4*>(&cold[4 * q]) = *reinterpret_cast<const float4*>(cp + 4 * q);
            }
            const float* xwp = g_xW + ((size_t)t * NB2 + b) * NG + col0 + ul0 * 4;
            #pragma unroll
            for (int i = 0; i < 16; i++) {
                float4 z4 = *reinterpret_cast<const float4*>(&zt[row * ZS + (ul0 + i) * 4]);
                float4 x4 = *reinterpret_cast<const float4*>(xwp + i * 4);
                float4 b4 = *reinterpret_cast<const float4*>(&s_bias[(ul0 + i) * 4]);
                float zi = z4.x + x4.x + b4.x;
                float zj = z4.y + x4.y + b4.y;
                float zf = z4.z + x4.z + b4.z;
                float zo = z4.w + x4.w + b4.w;
                float nc = cold[i] * sigmf(zf) + sigmf(zi) * tanhf(zj);
                float nh = tanhf(nc) * sigmf(zo);
                if (!valid) { nc = cold[i]; nh = hold[i]; }
                cold[i] = nc; hnew[i] = nh;
            }
            #pragma unroll
            for (int q = 0; q < 4; q++) {
                *reinterpret_cast<float4*>(cp + 4 * q) = *reinterpret_cast<float4*>(&cold[4 * q]);
                *reinterpret_cast<float4*>(hp + 4 * q) = *reinterpret_cast<float4*>(&hnew[4 * q]);
            }
            __nv_bfloat16* an = g_Abuf[(t + 1) & 1] + b * KCH + ct * 32 + ul0;
            #pragma unroll
            for (int i = 0; i < 8; i++) {
                float v0 = hnew[2 * i], v1 = hnew[2 * i + 1];
                __nv_bfloat16 h0 = __float2bfloat16_rn(v0);
                __nv_bfloat16 h1 = __float2bfloat16_rn(v1);
                __nv_bfloat162 hh; hh.x = h0; hh.y = h1;
                __nv_bfloat162 ll;
                ll.x = __float2bfloat16_rn(v0 - __bfloat162float(h0));
                ll.y = __float2bfloat16_rn(v1 - __bfloat162float(h1));
                *reinterpret_cast<__nv_bfloat162*>(an + 2 * i) = hh;
                *reinterpret_cast<__nv_bfloat162*>(an + KPH + 2 * i) = hh;
                *reinterpret_cast<__nv_bfloat162*>(an + 2 * KPH + 2 * i) = ll;
            }
        }
        if (t < NT - 1) grid_barrier();
    }
}

// ---------------------------------------------------------------------------
// SIMT 128x128 SGEMM for MLP layer 1: C = relu(A@B + aux[col])
// ---------------------------------------------------------------------------
__global__ void gemm128(const float* __restrict__ A, int lda,
                        const float* __restrict__ Bm, int ldb,
                        float* __restrict__ C, int ldc,
                        int K, const float* __restrict__ aux) {
    __shared__ float As[8][128];
    __shared__ float Bs[8][128];
    const int tid  = threadIdx.x;
    const int row0 = blockIdx.y * 128;
    const int col0 = blockIdx.x * 128;
    float acc[8][8];
    #pragma unroll
    for (int i = 0; i < 8; i++)
        #pragma unroll
        for (int j = 0; j < 8; j++) acc[i][j] = 0.0f;
    const int tr = (tid >> 4) << 3;
    const int tc = (tid & 15) << 3;
    for (int k0 = 0; k0 < K; k0 += 8) {
        #pragma unroll
        for (int i = 0; i < 4; i++) {
            int p = tid * 4 + i, ar = p >> 3, ak = p & 7;
            As[ak][ar] = (k0 + ak < K) ? A[(size_t)(row0 + ar) * lda + k0 + ak] : 0.0f;
        }
        #pragma unroll
        for (int i = 0; i < 4; i++) {
            int p = tid * 4 + i, bk = p >> 7, bc = p & 127;
            Bs[bk][bc] = (k0 + bk < K) ? Bm[(size_t)(k0 + bk) * ldb + col0 + bc] : 0.0f;
        }
        __syncthreads();
        #pragma unroll
        for (int kk = 0; kk < 8; kk++) {
            float ra[8], rb[8];
            #pragma unroll
            for (int i = 0; i < 8; i++) ra[i] = As[kk][tr + i];
            #pragma unroll
            for (int j = 0; j < 8; j++) rb[j] = Bs[kk][tc + j];
            #pragma unroll
            for (int i = 0; i < 8; i++)
                #pragma unroll
                for (int j = 0; j < 8; j++) acc[i][j] += ra[i] * rb[j];
        }
        __syncthreads();
    }
    #pragma unroll
    for (int i = 0; i < 8; i++)
        #pragma unroll
        for (int j = 0; j < 8; j++) {
            size_t idx = (size_t)(row0 + tr + i) * ldc + (col0 + tc + j);
            float v = acc[i][j] + aux[col0 + tc + j];
            C[idx] = v > 0.0f ? v : 0.0f;
        }
}

// ---------------------------------------------------------------------------
__global__ void combine(const int* __restrict__ sl1, const int* __restrict__ sl2) {
    int b = blockIdx.x;
    __shared__ float red[256];
    float len1 = (float)sl1[b] / (float)NT;
    float len2 = (float)sl2[b] / (float)NT;
    float lsum = 0.0f;
    float* hc = g_hc + (size_t)b * NHC;
    for (int k = threadIdx.x; k < NH + 1; k += 256) {
        float a = (k < NH) ? g_h[(size_t)b * NH + k]        : len1;
        float d = (k < NH) ? g_h[(size_t)(NB + b) * NH + k] : len2;
        float s = a - d;
        hc[k]        = a;
        hc[513 + k]  = d;
        hc[1026 + k] = s;
        hc[1540 + k] = a * d;
        lsum += s * s;
    }
    red[threadIdx.x] = lsum;
    __syncthreads();
    for (int s = 128; s > 0; s >>= 1) {
        if (threadIdx.x < s) red[threadIdx.x] += red[threadIdx.x + s];
        __syncthreads();
    }
    if (threadIdx.x == 0) hc[1539] = red[0];
}

__global__ void final_out(const float* __restrict__ W2, const float* __restrict__ b2,
                          float* __restrict__ out) {
    int b = blockIdx.x;
    __shared__ float s0[64], s1[64];
    float a0 = 0.0f, a1 = 0.0f;
    for (int k = threadIdx.x; k < NM; k += 64) {
        float e = g_e1[(size_t)b * NM + k];
        a0 += e * W2[k * 2 + 0];
        a1 += e * W2[k * 2 + 1];
    }
    s0[threadIdx.x] = a0;
    s1[threadIdx.x] = a1;
    __syncthreads();
    for (int s = 32; s > 0; s >>= 1) {
        if (threadIdx.x < s) { s0[threadIdx.x] += s0[threadIdx.x + s];
                               s1[threadIdx.x] += s1[threadIdx.x + s]; }
        __syncthreads();
    }
    if (threadIdx.x == 0) {
        out[b * 2 + 0] = s0[0] + b2[0];
        out[b * 2 + 1] = s1[0] + b2[1];
    }
}

// ---------------------------------------------------------------------------
extern "C" void kernel_launch(void* const* d_in, const int* in_sizes, int n_in,
                              void* d_out, int out_size) {
    const int*   in1 = (const int*)  d_in[0];
    const int*   in2 = (const int*)  d_in[1];
    const int*   sl1 = (const int*)  d_in[2];
    const int*   sl2 = (const int*)  d_in[3];
    const float* emb = (const float*)d_in[4];
    const float* lk  = (const float*)d_in[5];
    const float* lb  = (const float*)d_in[6];
    const float* W1  = (const float*)d_in[7];
    const float* b1  = (const float*)d_in[8];
    const float* W2  = (const float*)d_in[9];
    const float* b2  = (const float*)d_in[10];
    float* out = (float*)d_out;

    float *p_xW, *p_hc, *p_e1;
    __nv_bfloat16 *p_Bh, *p_Ax, *p_Bx;
    cudaGetSymbolAddress((void**)&p_xW, g_xW);
    cudaGetSymbolAddress((void**)&p_hc, g_hc);
    cudaGetSymbolAddress((void**)&p_e1, g_e1);
    cudaGetSymbolAddress((void**)&p_Bh, g_Bh);
    cudaGetSymbolAddress((void**)&p_Ax, g_Ax);
    cudaGetSymbolAddress((void**)&p_Bx, g_Bx);

    cudaFuncSetAttribute(gemm_mma, cudaFuncAttributeMaxDynamicSharedMemorySize, GEMM_SMEM);
    cudaFuncSetAttribute(lstm_persist, cudaFuncAttributeMaxDynamicSharedMemorySize, PERSIST_SMEM);

    const float* Wh = lk + (size_t)NE * NG;

    zero_init<<<(NB2 * NH + 255) / 256, 256>>>();
    build_B_perm<<<(NG * KPH + 255) / 256, 256>>>(Wh, p_Bh, NH, KPH);
    build_B_perm<<<(NG * KPX + 255) / 256, 256>>>(lk, p_Bx, NE, KPX);
    build_Ax<<<(NT * NB2 + 7) / 8, 256>>>(in1, in2, emb);

    // xproj: xW[all t] = emb' @ Wx'  (output cols gate-interleaved)
    gemm_mma<<<dim3(NG / 128, NT * NB2 / 128), 256, GEMM_SMEM>>>(p_Ax, p_Bx, p_xW, KCX, NCX);

    // entire recurrence in one persistent kernel
    lstm_persist<<<RCTAS, 256, PERSIST_SMEM>>>(p_Bh, lb, sl1, sl2);

    combine<<<NB, 256>>>(sl1, sl2);
    gemm128<<<dim3(NM / 128, NB / 128), 256>>>(p_hc, NHC, W1, NM, p_e1, NM, NHC, b1);
    final_out<<<NB, 64>>>(W2, b2, out);
}

// round 5
// speedup vs baseline: 1.1766x; 1.1766x over previous
#include <cuda_runtime.h>
#include <cuda_bf16.h>
#include <math.h>
#include <stdint.h>

#define NB   512
#define NT   60
#define NE   300
#define NH   512
#define NM   256
#define NB2  1024
#define NG   2048
#define NHC  2053

#define KPH  512
#define KCH  1536
#define NCH  24
#define KPX  320
#define KCX  960
#define NCX  15

#define STAGES 3
#define STAGE_BYTES 32768
#define GEMM_SMEM (STAGES*STAGE_BYTES)
#define ZS 136

__device__ float g_xW[(size_t)NT * NB2 * NG];      // gate-interleaved cols, sorted rows
__device__ float g_h [NB2 * NH];                   // sorted row order
__device__ float g_c [NB2 * NH];
__device__ float g_hc[NB * NHC];
__device__ float g_e1[NB * NM];
__device__ __nv_bfloat16 g_Abuf[2][(size_t)NB2 * KCH];   // ping-pong A' [hi|hi|lo], sorted rows
__device__ __nv_bfloat16 g_Bh[(size_t)NG * KCH];
__device__ __nv_bfloat16 g_Ax[(size_t)NT * NB2 * KCX];
__device__ __nv_bfloat16 g_Bx[(size_t)NG * KCX];
__device__ int g_perm[NB2];    // pos -> original row
__device__ int g_pos [NB2];    // original row -> pos
__device__ int g_slp [NB2];    // seqlen at pos
__device__ int g_Mt  [NT];     // #active rows at step t

__device__ __forceinline__ float sigmf(float x) { return 1.0f / (1.0f + expf(-x)); }

#define SWZ(b) ((b) ^ (((b) >> 3) & 0x70))

__device__ __forceinline__ uint32_t smem_u32(const void* p) {
    uint32_t a;
    asm("{ .reg .u64 t; cvta.to.shared.u64 t, %1; cvt.u32.u64 %0, t; }" : "=r"(a) : "l"(p));
    return a;
}
__device__ __forceinline__ void cpasync16(uint32_t dst, const void* src) {
    asm volatile("cp.async.cg.shared.global [%0], [%1], 16;"
                 :: "r"(dst), "l"(__cvta_generic_to_global(src)));
}
#define CP_COMMIT() asm volatile("cp.async.commit_group;" ::: "memory")

__device__ __forceinline__ void ldsm_x4(uint32_t& r0, uint32_t& r1, uint32_t& r2, uint32_t& r3,
                                        uint32_t addr) {
    asm volatile("ldmatrix.sync.aligned.m8n8.x4.shared.b16 {%0,%1,%2,%3}, [%4];"
                 : "=r"(r0), "=r"(r1), "=r"(r2), "=r"(r3) : "r"(addr));
}
__device__ __forceinline__ void mma_bf16(float* c, const uint32_t* a, uint32_t b0, uint32_t b1) {
    asm volatile("mma.sync.aligned.m16n8k16.row.col.f32.bf16.bf16.f32 "
                 "{%0,%1,%2,%3}, {%4,%5,%6,%7}, {%8,%9}, {%0,%1,%2,%3};"
                 : "+f"(c[0]), "+f"(c[1]), "+f"(c[2]), "+f"(c[3])
                 : "r"(a[0]), "r"(a[1]), "r"(a[2]), "r"(a[3]), "r"(b0), "r"(b1));
}

// ---------------------------------------------------------------------------
__global__ void zero_init() {
    int i = blockIdx.x * 256 + threadIdx.x;
    if (i < NB2 * NH) { g_h[i] = 0.0f; g_c[i] = 0.0f; }
}

// ---------------------------------------------------------------------------
// Counting sort of the 1024 rows by seqlen descending (1 CTA).
// ---------------------------------------------------------------------------
__global__ void sort_rows(const int* __restrict__ sl1, const int* __restrict__ sl2) {
    __shared__ int cnt[64];
    __shared__ int off[64];
    int tid = threadIdx.x;
    if (tid < 64) cnt[tid] = 0;
    __syncthreads();
    int sl = (tid < NB) ? sl1[tid] : sl2[tid - NB];
    atomicAdd(&cnt[sl], 1);
    __syncthreads();
    if (tid == 0) {
        int acc = 0;
        for (int s = 60; s >= 1; s--) { off[s] = acc; acc += cnt[s]; }
    }
    __syncthreads();
    int pos = atomicAdd(&off[sl], 1);
    g_perm[pos] = tid;
    g_pos[tid]  = pos;
    g_slp[pos]  = sl;
    __syncthreads();
    if (tid < NT) {
        int m = 0;
        for (int s = tid + 1; s <= 60; s++) m += cnt[s];
        g_Mt[tid] = m;
    }
}

// ---------------------------------------------------------------------------
// B' build with gate-interleaved N permutation + hi/lo K split [hi|lo|hi]
// ---------------------------------------------------------------------------
__global__ void build_B_perm(const float* __restrict__ W, __nv_bfloat16* __restrict__ dst,
                             int Ksrc, int Kp) {
    int idx = blockIdx.x * 256 + threadIdx.x;
    if (idx >= NG * Kp) return;
    int k = idx / NG;
    int n = idx % NG;
    int nsrc = (n & 3) * 512 + (n >> 2);
    float v = (k < Ksrc) ? W[(size_t)k * NG + nsrc] : 0.0f;
    __nv_bfloat16 hi = __float2bfloat16_rn(v);
    __nv_bfloat16 lo = __float2bfloat16_rn(v - __bfloat162float(hi));
    size_t base = (size_t)n * (3 * Kp);
    dst[base + k] = hi;
    dst[base + Kp + k] = lo;
    dst[base + 2 * Kp + k] = hi;
}

// ---------------------------------------------------------------------------
// Gathered A' for xproj (sorted row order), skip inactive (pos >= Mt[t])
// ---------------------------------------------------------------------------
__global__ void build_Ax(const int* __restrict__ in1, const int* __restrict__ in2,
                         const float* __restrict__ emb) {
    int w = blockIdx.x * 8 + (threadIdx.x >> 5);
    int lane = threadIdx.x & 31;
    if (w >= NT * NB2) return;
    int t   = w >> 10;
    int pos = w & 1023;
    if (pos >= g_Mt[t]) return;
    int b2 = g_perm[pos];
    int tok = (b2 < NB) ? in1[b2 * NT + t] : in2[(b2 - NB) * NT + t];
    const float* er = emb + (size_t)tok * NE;
    size_t base = (size_t)w * KCX;
    for (int k = lane; k < KPX; k += 32) {
        float v = (k < NE) ? er[k] : 0.0f;
        __nv_bfloat16 hi = __float2bfloat16_rn(v);
        __nv_bfloat16 lo = __float2bfloat16_rn(v - __bfloat162float(hi));
        g_Ax[base + k] = hi;
        g_Ax[base + KPX + k] = hi;
        g_Ax[base + 2 * KPX + k] = lo;
    }
}

// ---------------------------------------------------------------------------
// bf16 mma.sync GEMM (xproj): skips row tiles fully past Mt
// ---------------------------------------------------------------------------
__global__ void __launch_bounds__(256, 2)
gemm_mma(const __nv_bfloat16* __restrict__ A, const __nv_bfloat16* __restrict__ B,
         float* __restrict__ C, int ldab, int NC) {
    extern __shared__ char dsm[];
    const int tid  = threadIdx.x;
    const int wid  = tid >> 5;
    const int lane = tid & 31;
    {   // xproj row-tile skip: blockIdx.y = t*8 + l
        int t = blockIdx.y >> 3, l = blockIdx.y & 7;
        if (l * 128 >= g_Mt[t]) return;
    }
    const int row0 = blockIdx.y * 128;
    const int col0 = blockIdx.x * 128;
    const int wm0  = (wid & 1) * 64;
    const int wn0  = (wid >> 1) * 32;
    const uint32_t sm = smem_u32(dsm);

    const __nv_bfloat16* aRow = A + (size_t)row0 * ldab;
    const __nv_bfloat16* bRow = B + (size_t)col0 * ldab;

    auto load_chunk = [&](int c, int st) {
        uint32_t aB = sm + st * STAGE_BYTES;
        uint32_t bB = aB + 16384;
        const __nv_bfloat16* aS = aRow + c * 64;
        const __nv_bfloat16* bS = bRow + c * 64;
        #pragma unroll
        for (int i = 0; i < 4; i++) {
            int idx = i * 256 + tid;
            int r = idx >> 3, s = idx & 7;
            cpasync16(aB + SWZ(r * 128 + s * 16), aS + (size_t)r * ldab + s * 8);
        }
        #pragma unroll
        for (int i = 0; i < 4; i++) {
            int idx = i * 256 + tid;
            int n = idx >> 3, s = idx & 7;
            cpasync16(bB + SWZ(n * 128 + s * 16), bS + (size_t)n * ldab + s * 8);
        }
    };

    float acc[4][4][4];
    #pragma unroll
    for (int i = 0; i < 4; i++)
        #pragma unroll
        for (int j = 0; j < 4; j++)
            #pragma unroll
            for (int k = 0; k < 4; k++) acc[i][j][k] = 0.0f;

    for (int s = 0; s < STAGES && s < NC; s++) { load_chunk(s, s); CP_COMMIT(); }

    const int a_row = wm0 + (lane & 15);
    const int a_colb = 16 * (lane >> 4);
    const int b_row = wn0 + lane;
    for (int c = 0; c < NC; c++) {
        int st = c % STAGES;
        int rem = NC - 1 - c;
        if (rem >= 2)      asm volatile("cp.async.wait_group 2;" ::: "memory");
        else if (rem == 1) asm volatile("cp.async.wait_group 1;" ::: "memory");
        else               asm volatile("cp.async.wait_group 0;" ::: "memory");
        __syncthreads();

        uint32_t aB = sm + st * STAGE_BYTES;
        uint32_t bB = aB + 16384;
        #pragma unroll
        for (int kk = 0; kk < 4; kk++) {
            uint32_t a[4][4];
            #pragma unroll
            for (int mf = 0; mf < 4; mf++) {
                uint32_t addr = aB + SWZ((a_row + mf * 16) * 128 + kk * 32 + a_colb);
                ldsm_x4(a[mf][0], a[mf][1], a[mf][2], a[mf][3], addr);
            }
            uint32_t blo[4], bhi[4];
            uint32_t addr0 = bB + SWZ(b_row * 128 + kk * 32);
            ldsm_x4(blo[0], blo[1], blo[2], blo[3], addr0);
            uint32_t addr1 = bB + SWZ(b_row * 128 + kk * 32 + 16);
            ldsm_x4(bhi[0], bhi[1], bhi[2], bhi[3], addr1);
            #pragma unroll
            for (int mf = 0; mf < 4; mf++)
                #pragma unroll
                for (int nf = 0; nf < 4; nf++)
                    mma_bf16(acc[mf][nf], a[mf], blo[nf], bhi[nf]);
        }
        __syncthreads();
        if (c + STAGES < NC) { load_chunk(c + STAGES, st); CP_COMMIT(); }
    }

    const int gid = lane >> 2, tig = lane & 3;
    #pragma unroll
    for (int mf = 0; mf < 4; mf++)
        #pragma unroll
        for (int nf = 0; nf < 4; nf++) {
            size_t row = (size_t)row0 + wm0 + mf * 16 + gid;
            size_t col = (size_t)col0 + wn0 + nf * 8 + tig * 2;
            *reinterpret_cast<float2*>(C + row * NG + col) =
                make_float2(acc[mf][nf][0], acc[mf][nf][1]);
            *reinterpret_cast<float2*>(C + (row + 8) * NG + col) =
                make_float2(acc[mf][nf][2], acc[mf][nf][3]);
        }
}

// ---------------------------------------------------------------------------
// One recurrence step: z = A'@B' (tile) + fused LSTM cell. Early exit past Mt.
// z tile aliases the (finished) GEMM stage smem.
// ---------------------------------------------------------------------------
__global__ void __launch_bounds__(256)
gemm_step(const __nv_bfloat16* __restrict__ Bh, const float* __restrict__ bias, int t) {
    extern __shared__ char dsm[];
    float* zt = (float*)dsm;          // reused after MMA
    __shared__ float s_bias[128];

    const int tid  = threadIdx.x;
    const int wid  = tid >> 5;
    const int lane = tid & 31;
    const int rt = blockIdx.y, ct = blockIdx.x;
    const int row0 = rt * 128, col0 = ct * 128;
    if (row0 >= g_Mt[t]) return;
    const int wm0 = (wid & 1) * 64, wn0 = (wid >> 1) * 32;
    const uint32_t sm = smem_u32(dsm);

    if (tid < 128) {
        int u = ct * 32 + (tid >> 2), g = tid & 3;
        s_bias[tid] = bias[g * 512 + u] + ((g == 2) ? 1.0f : 0.0f);
    }

    float acc[4][4][4];
    #pragma unroll
    for (int i = 0; i < 4; i++)
        #pragma unroll
        for (int j = 0; j < 4; j++)
            #pragma unroll
            for (int k = 0; k < 4; k++) acc[i][j][k] = 0.0f;

    const int gid = lane >> 2, tig = lane & 3;

    if (t > 0) {
        const __nv_bfloat16* aRow = g_Abuf[t & 1] + (size_t)row0 * KCH;
        const __nv_bfloat16* bRow = Bh + (size_t)col0 * KCH;
        auto load_chunk = [&](int c, int st) {
            uint32_t aB = sm + st * STAGE_BYTES;
            uint32_t bB = aB + 16384;
            const __nv_bfloat16* aS = aRow + c * 64;
            const __nv_bfloat16* bS = bRow + c * 64;
            #pragma unroll
            for (int i = 0; i < 4; i++) {
                int idx = i * 256 + tid;
                int r = idx >> 3, s = idx & 7;
                cpasync16(aB + SWZ(r * 128 + s * 16), aS + (size_t)r * KCH + s * 8);
            }
            #pragma unroll
            for (int i = 0; i < 4; i++) {
                int idx = i * 256 + tid;
                int n = idx >> 3, s = idx & 7;
                cpasync16(bB + SWZ(n * 128 + s * 16), bS + (size_t)n * KCH + s * 8);
            }
        };
        const int a_row = wm0 + (lane & 15);
        const int a_colb = 16 * (lane >> 4);
        const int b_row = wn0 + lane;
        for (int s = 0; s < STAGES; s++) { load_chunk(s, s); CP_COMMIT(); }
        for (int c = 0; c < NCH; c++) {
            int st = c % STAGES;
            int rem = NCH - 1 - c;
            if (rem >= 2)      asm volatile("cp.async.wait_group 2;" ::: "memory");
            else if (rem == 1) asm volatile("cp.async.wait_group 1;" ::: "memory");
            else               asm volatile("cp.async.wait_group 0;" ::: "memory");
            __syncthreads();
            uint32_t aB = sm + st * STAGE_BYTES;
            uint32_t bB = aB + 16384;
            #pragma unroll
            for (int kk = 0; kk < 4; kk++) {
                uint32_t a[4][4];
                #pragma unroll
                for (int mf = 0; mf < 4; mf++) {
                    uint32_t addr = aB + SWZ((a_row + mf * 16) * 128 + kk * 32 + a_colb);
                    ldsm_x4(a[mf][0], a[mf][1], a[mf][2], a[mf][3], addr);
                }
                uint32_t blo[4], bhi[4];
                uint32_t addr0 = bB + SWZ(b_row * 128 + kk * 32);
                ldsm_x4(blo[0], blo[1], blo[2], blo[3], addr0);
                uint32_t addr1 = bB + SWZ(b_row * 128 + kk * 32 + 16);
                ldsm_x4(bhi[0], bhi[1], bhi[2], bhi[3], addr1);
                #pragma unroll
                for (int mf = 0; mf < 4; mf++)
                    #pragma unroll
                    for (int nf = 0; nf < 4; nf++)
                        mma_bf16(acc[mf][nf], a[mf], blo[nf], bhi[nf]);
            }
            __syncthreads();
            if (c + STAGES < NCH) { load_chunk(c + STAGES, st); CP_COMMIT(); }
        }
    }
    __syncthreads();   // all MMA smem reads done before z overwrite

    #pragma unroll
    for (int mf = 0; mf < 4; mf++)
        #pragma unroll
        for (int nf = 0; nf < 4; nf++) {
            int r = wm0 + mf * 16 + gid;
            int cc = wn0 + nf * 8 + tig * 2;
            *reinterpret_cast<float2*>(&zt[r * ZS + cc]) =
                make_float2(acc[mf][nf][0], acc[mf][nf][1]);
            *reinterpret_cast<float2*>(&zt[(r + 8) * ZS + cc]) =
                make_float2(acc[mf][nf][2], acc[mf][nf][3]);
        }
    __syncthreads();

    // fused LSTM cell: 2 threads per row, 16 units each
    {
        int row = tid >> 1;
        int ul0 = (tid & 1) * 16;
        size_t b = (size_t)row0 + row;
        bool valid = t < g_slp[b];
        float hold[16], cold[16], hnew[16];
        float* hp = g_h + b * NH + ct * 32 + ul0;
        float* cp = g_c + b * NH + ct * 32 + ul0;
        #pragma unroll
        for (int q = 0; q < 4; q++) {
            *reinterpret_cast<float4*>(&hold[4 * q]) = *reinterpret_cast<const float4*>(hp + 4 * q);
            *reinterpret_cast<float4*>(&cold[4 * q]) = *reinterpret_cast<const float4*>(cp + 4 * q);
        }
        const float* xwp = g_xW + ((size_t)t * NB2 + b) * NG + col0 + ul0 * 4;
        #pragma unroll
        for (int i = 0; i < 16; i++) {
            float4 z4 = *reinterpret_cast<const float4*>(&zt[row * ZS + (ul0 + i) * 4]);
            float4 x4 = *reinterpret_cast<const float4*>(xwp + i * 4);
            float4 b4 = *reinterpret_cast<const float4*>(&s_bias[(ul0 + i) * 4]);
            float zi = z4.x + x4.x + b4.x;
            float zj = z4.y + x4.y + b4.y;
            float zf = z4.z + x4.z + b4.z;
            float zo = z4.w + x4.w + b4.w;
            float nc = cold[i] * sigmf(zf) + sigmf(zi) * tanhf(zj);
            float nh = tanhf(nc) * sigmf(zo);
            cold[i] = nc; hnew[i] = nh;
        }
        if (valid) {
            #pragma unroll
            for (int q = 0; q < 4; q++) {
                *reinterpret_cast<float4*>(cp + 4 * q) = *reinterpret_cast<float4*>(&cold[4 * q]);
                *reinterpret_cast<float4*>(hp + 4 * q) = *reinterpret_cast<float4*>(&hnew[4 * q]);
            }
            __nv_bfloat16* an = g_Abuf[(t + 1) & 1] + b * KCH + ct * 32 + ul0;
            #pragma unroll
            for (int i = 0; i < 8; i++) {
                float v0 = hnew[2 * i], v1 = hnew[2 * i + 1];
                __nv_bfloat16 h0 = __float2bfloat16_rn(v0);
                __nv_bfloat16 h1 = __float2bfloat16_rn(v1);
                __nv_bfloat162 hh; hh.x = h0; hh.y = h1;
                __nv_bfloat162 ll;
                ll.x = __float2bfloat16_rn(v0 - __bfloat162float(h0));
                ll.y = __float2bfloat16_rn(v1 - __bfloat162float(h1));
                *reinterpret_cast<__nv_bfloat162*>(an + 2 * i) = hh;
                *reinterpret_cast<__nv_bfloat162*>(an + KPH + 2 * i) = hh;
                *reinterpret_cast<__nv_bfloat162*>(an + 2 * KPH + 2 * i) = ll;
            }
        }
    }
}

// ---------------------------------------------------------------------------
// SIMT 128x128 SGEMM for MLP layer 1: C = relu(A@B + aux[col])
// ---------------------------------------------------------------------------
__global__ void gemm128(const float* __restrict__ A, int lda,
                        const float* __restrict__ Bm, int ldb,
                        float* __restrict__ C, int ldc,
                        int K, const float* __restrict__ aux) {
    __shared__ float As[8][128];
    __shared__ float Bs[8][128];
    const int tid  = threadIdx.x;
    const int row0 = blockIdx.y * 128;
    const int col0 = blockIdx.x * 128;
    float acc[8][8];
    #pragma unroll
    for (int i = 0; i < 8; i++)
        #pragma unroll
        for (int j = 0; j < 8; j++) acc[i][j] = 0.0f;
    const int tr = (tid >> 4) << 3;
    const int tc = (tid & 15) << 3;
    for (int k0 = 0; k0 < K; k0 += 8) {
        #pragma unroll
        for (int i = 0; i < 4; i++) {
            int p = tid * 4 + i, ar = p >> 3, ak = p & 7;
            As[ak][ar] = (k0 + ak < K) ? A[(size_t)(row0 + ar) * lda + k0 + ak] : 0.0f;
        }
        #pragma unroll
        for (int i = 0; i < 4; i++) {
            int p = tid * 4 + i, bk = p >> 7, bc = p & 127;
            Bs[bk][bc] = (k0 + bk < K) ? Bm[(size_t)(k0 + bk) * ldb + col0 + bc] : 0.0f;
        }
        __syncthreads();
        #pragma unroll
        for (int kk = 0; kk < 8; kk++) {
            float ra[8], rb[8];
            #pragma unroll
            for (int i = 0; i < 8; i++) ra[i] = As[kk][tr + i];
            #pragma unroll
            for (int j = 0; j < 8; j++) rb[j] = Bs[kk][tc + j];
            #pragma unroll
            for (int i = 0; i < 8; i++)
                #pragma unroll
                for (int j = 0; j < 8; j++) acc[i][j] += ra[i] * rb[j];
        }
        __syncthreads();
    }
    #pragma unroll
    for (int i = 0; i < 8; i++)
        #pragma unroll
        for (int j = 0; j < 8; j++) {
            size_t idx = (size_t)(row0 + tr + i) * ldc + (col0 + tc + j);
            float v = acc[i][j] + aux[col0 + tc + j];
            C[idx] = v > 0.0f ? v : 0.0f;
        }
}

// ---------------------------------------------------------------------------
__global__ void combine(const int* __restrict__ sl1, const int* __restrict__ sl2) {
    int b = blockIdx.x;
    __shared__ float red[256];
    float len1 = (float)sl1[b] / (float)NT;
    float len2 = (float)sl2[b] / (float)NT;
    int p1 = g_pos[b], p2 = g_pos[NB + b];
    float lsum = 0.0f;
    float* hc = g_hc + (size_t)b * NHC;
    for (int k = threadIdx.x; k < NH + 1; k += 256) {
        float a = (k < NH) ? g_h[(size_t)p1 * NH + k] : len1;
        float d = (k < NH) ? g_h[(size_t)p2 * NH + k] : len2;
        float s = a - d;
        hc[k]        = a;
        hc[513 + k]  = d;
        hc[1026 + k] = s;
        hc[1540 + k] = a * d;
        lsum += s * s;
    }
    red[threadIdx.x] = lsum;
    __syncthreads();
    for (int s = 128; s > 0; s >>= 1) {
        if (threadIdx.x < s) red[threadIdx.x] += red[threadIdx.x + s];
        __syncthreads();
    }
    if (threadIdx.x == 0) hc[1539] = red[0];
}

__global__ void final_out(const float* __restrict__ W2, const float* __restrict__ b2,
                          float* __restrict__ out) {
    int b = blockIdx.x;
    __shared__ float s0[64], s1[64];
    float a0 = 0.0f, a1 = 0.0f;
    for (int k = threadIdx.x; k < NM; k += 64) {
        float e = g_e1[(size_t)b * NM + k];
        a0 += e * W2[k * 2 + 0];
        a1 += e * W2[k * 2 + 1];
    }
    s0[threadIdx.x] = a0;
    s1[threadIdx.x] = a1;
    __syncthreads();
    for (int s = 32; s > 0; s >>= 1) {
        if (threadIdx.x < s) { s0[threadIdx.x] += s0[threadIdx.x + s];
                               s1[threadIdx.x] += s1[threadIdx.x + s]; }
        __syncthreads();
    }
    if (threadIdx.x == 0) {
        out[b * 2 + 0] = s0[0] + b2[0];
        out[b * 2 + 1] = s1[0] + b2[1];
    }
}

// ---------------------------------------------------------------------------
extern "C" void kernel_launch(void* const* d_in, const int* in_sizes, int n_in,
                              void* d_out, int out_size) {
    const int*   in1 = (const int*)  d_in[0];
    const int*   in2 = (const int*)  d_in[1];
    const int*   sl1 = (const int*)  d_in[2];
    const int*   sl2 = (const int*)  d_in[3];
    const float* emb = (const float*)d_in[4];
    const float* lk  = (const float*)d_in[5];
    const float* lb  = (const float*)d_in[6];
    const float* W1  = (const float*)d_in[7];
    const float* b1  = (const float*)d_in[8];
    const float* W2  = (const float*)d_in[9];
    const float* b2  = (const float*)d_in[10];
    float* out = (float*)d_out;

    float *p_xW, *p_hc, *p_e1;
    __nv_bfloat16 *p_Bh, *p_Ax, *p_Bx;
    cudaGetSymbolAddress((void**)&p_xW, g_xW);
    cudaGetSymbolAddress((void**)&p_hc, g_hc);
    cudaGetSymbolAddress((void**)&p_e1, g_e1);
    cudaGetSymbolAddress((void**)&p_Bh, g_Bh);
    cudaGetSymbolAddress((void**)&p_Ax, g_Ax);
    cudaGetSymbolAddress((void**)&p_Bx, g_Bx);

    cudaFuncSetAttribute(gemm_mma, cudaFuncAttributeMaxDynamicSharedMemorySize, GEMM_SMEM);
    cudaFuncSetAttribute(gemm_step, cudaFuncAttributeMaxDynamicSharedMemorySize, GEMM_SMEM);

    const float* Wh = lk + (size_t)NE * NG;

    zero_init<<<(NB2 * NH + 255) / 256, 256>>>();
    sort_rows<<<1, NB2>>>(sl1, sl2);
    build_B_perm<<<(NG * KPH + 255) / 256, 256>>>(Wh, p_Bh, NH, KPH);
    build_B_perm<<<(NG * KPX + 255) / 256, 256>>>(lk, p_Bx, NE, KPX);
    build_Ax<<<(NT * NB2 + 7) / 8, 256>>>(in1, in2, emb);

    gemm_mma<<<dim3(NG / 128, NT * NB2 / 128), 256, GEMM_SMEM>>>(p_Ax, p_Bx, p_xW, KCX, NCX);

    for (int t = 0; t < NT; t++)
        gemm_step<<<dim3(16, 8), 256, GEMM_SMEM>>>(p_Bh, lb, t);

    combine<<<NB, 256>>>(sl1, sl2);
    gemm128<<<dim3(NM / 128, NB / 128), 256>>>(p_hc, NHC, W1, NM, p_e1, NM, NHC, b1);
    final_out<<<NB, 64>>>(W2, b2, out);
}